// round 4
// baseline (speedup 1.0000x reference)
#include <cuda_runtime.h>
#include <cstdint>

#define TT 2048
#define BB 128
#define HH 200
#define CH 56        // logical k-span per chunk (4 chunks cover padded 224)
#define CSTRIDE 60   // float stride between chunks in hsm (bank-conflict-free)
#define HROW (4 * CSTRIDE)  // 240 floats per h buffer

typedef unsigned long long ull;

__device__ __forceinline__ ull pack2(float lo, float hi) {
    ull r; asm("mov.b64 %0, {%1,%2};" : "=l"(r) : "f"(lo), "f"(hi)); return r;
}
__device__ __forceinline__ void fma2(ull& acc, ull a, ull b) {
    asm("fma.rn.f32x2 %0, %1, %2, %0;" : "+l"(acc) : "l"(a), "l"(b));
}
__device__ __forceinline__ void unpack2(ull v, float& lo, float& hi) {
    asm("mov.b64 {%0,%1}, %2;" : "=f"(lo), "=f"(hi) : "l"(v));
}
// tanh(x) = 1 - 2/(exp2(2x*log2e)+1)
__device__ __forceinline__ float tanh_fast(float x) {
    float e; asm("ex2.approx.ftz.f32 %0, %1;" : "=f"(e) : "f"(x * 2.885390082f));
    float r; asm("rcp.approx.ftz.f32 %0, %1;" : "=f"(r) : "f"(e + 1.0f));
    return fmaf(-2.0f, r, 1.0f);
}

// 800 threads = 25 warps. Warp w, lane l: neuron j = 8w + (l>>2), k-group kg = l&3.
// Thread (j,kg) holds W_hh[j, 56kg : 56kg+56) packed as 28 u64 pairs (zeros past H).
// kg==3 extras: wr[26]=(Wih[j,0],Wih[j,1]), wr[27]=(bias_j,0); matching h-pad slots
// carry (x_t0, x_t1, 1, 0) so the dot product directly yields the pre-activation.
__global__ void __launch_bounds__(800, 1) rnn_kernel(
    const float* __restrict__ x,     // [T, B, 2]
    const float* __restrict__ Wih,   // [H, 2]
    const float* __restrict__ Whh,   // [H, H]
    const float* __restrict__ bih,   // [H]
    const float* __restrict__ bhh,   // [H]
    const float* __restrict__ Wout,  // [1, H]
    const float* __restrict__ bOut,  // [1]
    float* __restrict__ out)         // [T, B, 1]
{
    __shared__ __align__(16) float2 xsm[TT + 1];     // this batch's inputs
    __shared__ __align__(16) float  hsm[2][HROW];    // double-buffered h (+pads)
    __shared__ __align__(16) float  houtsm[2][HH];   // h_j * Wout_j, per step parity

    const int tid  = threadIdx.x;
    const int b    = blockIdx.x;
    const int w    = tid >> 5;
    const int lane = tid & 31;
    const int kg   = lane & 3;
    const int j    = 8 * w + (lane >> 2);          // 0..199
    const int kbase = CH * kg;
    const bool leader  = (kg == 0);
    const bool outwarp = (w == 24);
    const int cj   = j / CH;                        // chunk holding neuron j
    const int hoff = cj * CSTRIDE + (j - cj * CH);  // j's slot in an h buffer

    // Preload input sequence for this batch
    for (int i = tid; i < TT; i += 800)
        xsm[i] = *(const float2*)(x + ((size_t)i * BB + b) * 2);

    // W_hh row j, chunk kg, as packed fp32 pairs (contiguous in gmem)
    ull wr[28];
    {
        const float* wrow = Whh + (size_t)j * HH;
#pragma unroll
        for (int i = 0; i < 28; i++) {
            int k = kbase + 2 * i;
            wr[i] = (k + 1 < HH) ? *(const ull*)(wrow + k) : 0ull;
        }
    }
    if (kg == 3) {
        wr[26] = pack2(Wih[2 * j], Wih[2 * j + 1]);   // pairs with (x0, x1)
        wr[27] = pack2(bih[j] + bhh[j], 0.0f);        // pairs with (1, 0)
    }
    const float wout = Wout[j];

    // Zero both h buffers (h_0 = 0, pads = 0), then set constant/x pad slots.
    for (int i = tid; i < 2 * HROW; i += 800) ((float*)hsm)[i] = 0.0f;
    __syncthreads();
    if (tid == 0) {
        float2 x0 = xsm[0];
        hsm[0][3 * CSTRIDE + 52] = x0.x;   // k=220 slot
        hsm[0][3 * CSTRIDE + 53] = x0.y;   // k=221
        hsm[0][3 * CSTRIDE + 54] = 1.0f;   // k=222 (bias carrier)
        hsm[1][3 * CSTRIDE + 54] = 1.0f;
    }
    __syncthreads();

    auto step = [&](int t, int p) {
        // dot over this thread's k-chunk; xproj+bias folded in via pad slots
        const ulonglong2* hp = (const ulonglong2*)(&hsm[p][CSTRIDE * kg]);
        ull a0 = 0ull, a1 = 0ull;
#pragma unroll
        for (int i = 0; i < 14; i++) {
            ulonglong2 hv = hp[i];                  // LDS.128, conflict-free
            fma2(a0, hv.x, wr[2 * i]);
            fma2(a1, hv.y, wr[2 * i + 1]);
        }
        float s0, s1, s2, s3;
        unpack2(a0, s0, s1);
        unpack2(a1, s2, s3);
        float s = (s0 + s1) + (s2 + s3);
        s += __shfl_xor_sync(0xFFFFFFFFu, s, 1);
        s += __shfl_xor_sync(0xFFFFFFFFu, s, 2);    // all 4 lanes: full pre-activation
        float h = tanh_fast(s);
        if (leader) {
            hsm[p ^ 1][hoff] = h;
            houtsm[t & 1][j] = h * wout;
        }
        if (tid == 0) {                              // stage x_{t+1} into next buffer
            float2 xn = xsm[t + 1];
            hsm[p ^ 1][3 * CSTRIDE + 52] = xn.x;
            hsm[p ^ 1][3 * CSTRIDE + 53] = xn.y;
        }
        if (outwarp && t > 0) {                      // reduce previous step's output
            float acc = 0.0f;
#pragma unroll
            for (int i = 0; i < 7; i++) {
                int idx = lane + 32 * i;
                if (idx < HH) acc += houtsm[(t - 1) & 1][idx];
            }
#pragma unroll
            for (int off = 16; off; off >>= 1)
                acc += __shfl_xor_sync(0xFFFFFFFFu, acc, off);
            if (lane == 0) out[(size_t)(t - 1) * BB + b] = acc + bOut[0];
        }
        __syncthreads();
    };

#pragma unroll 1
    for (int t = 0; t < TT; t += 2) {
        step(t, 0);
        step(t + 1, 1);
    }

    // Final timestep's output (t = TT-1, parity 1)
    if (outwarp) {
        float acc = 0.0f;
#pragma unroll
        for (int i = 0; i < 7; i++) {
            int idx = lane + 32 * i;
            if (idx < HH) acc += houtsm[1][idx];
        }
#pragma unroll
        for (int off = 16; off; off >>= 1)
            acc += __shfl_xor_sync(0xFFFFFFFFu, acc, off);
        if (lane == 0) out[(size_t)(TT - 1) * BB + b] = acc + bOut[0];
    }
}

extern "C" void kernel_launch(void* const* d_in, const int* in_sizes, int n_in,
                              void* d_out, int out_size) {
    const float* input_seq = (const float*)d_in[0];  // [T,B,2]
    const float* W_ih      = (const float*)d_in[1];  // [H,2]
    const float* W_hh      = (const float*)d_in[2];  // [H,H]
    const float* b_ih      = (const float*)d_in[3];  // [H]
    const float* b_hh      = (const float*)d_in[4];  // [H]
    const float* W_out     = (const float*)d_in[5];  // [1,H]
    const float* b_out     = (const float*)d_in[6];  // [1]
    float* out = (float*)d_out;                      // [T,B,1]

    rnn_kernel<<<BB, 800>>>(input_seq, W_ih, W_hh, b_ih, b_hh, W_out, b_out, out);
}

// round 5
// speedup vs baseline: 2.6580x; 2.6580x over previous
#include <cuda_runtime.h>
#include <cstdint>

#define TT 2048
#define BB 128
#define HH 200
#define NC 4          // k-chunks
#define CW 50         // real k-span per chunk
#define CS 52         // chunk stride in hsm (floats): 208B apart -> conflict-free LDS

typedef unsigned long long ull;

__device__ __forceinline__ void fma2(ull& acc, ull a, ull b) {
    asm("fma.rn.f32x2 %0, %1, %2, %0;" : "+l"(acc) : "l"(a), "l"(b));
}
__device__ __forceinline__ void unpack2(ull v, float& lo, float& hi) {
    asm("mov.b64 {%0,%1}, %2;" : "=f"(lo), "=f"(hi) : "l"(v));
}
__device__ __forceinline__ float tanh_hw(float x) {
    float r; asm("tanh.approx.f32 %0, %1;" : "=f"(r) : "f"(x));
    return r;
}

// Block: 832 threads = 26 warps, one CTA per batch row b.
//  warps 0-24 (tid<800): compute. kc = tid/200 (0..3), j = tid%200.
//    thread owns dot-partial of W_hh[j, 50kc : 50kc+50) with h.
//  tid<200 (also kc==0): epilogue in phase B (reduce partials, tanh, write h).
//  warp 25 (tid 800-831): output-head reduction for step t-1, overlapped with phase A.
__global__ void __launch_bounds__(832, 1) rnn_kernel(
    const float* __restrict__ x,     // [T, B, 2]
    const float* __restrict__ Wih,   // [H, 2]
    const float* __restrict__ Whh,   // [H, H]
    const float* __restrict__ bih,   // [H]
    const float* __restrict__ bhh,   // [H]
    const float* __restrict__ Wout,  // [1, H]
    const float* __restrict__ bOut,  // [1]
    float* __restrict__ out)         // [T, B, 1]
{
    __shared__ __align__(16) float2 xsm[TT];          // 16 KB input sequence
    __shared__ __align__(16) float  hsm[NC * CS];     // h, chunked layout (+pads)
    __shared__ __align__(16) float  part[3 * HH];     // partials from kc=1..3
    __shared__ __align__(16) float  houtsm[2][HH];    // h_j * Wout_j, parity buffers

    const int tid  = threadIdx.x;
    const int b    = blockIdx.x;
    const int lane = tid & 31;
    const int kc   = tid / HH;       // 0..3 for compute threads
    const int j    = tid - kc * HH;
    const bool compute = (tid < 800);
    const bool outwarp = (tid >= 800);

    // Preload this batch's inputs
    for (int i = tid; i < TT; i += 832)
        xsm[i] = *(const float2*)(x + ((size_t)i * BB + b) * 2);

    // W_hh row j, chunk kc: 25 packed pairs (+1 zero pad pair)
    ull wr[26];
    if (compute) {
        const float* wrow = Whh + (size_t)j * HH + CW * kc;  // 8B aligned (50kc even)
#pragma unroll
        for (int i = 0; i < 25; i++) wr[i] = *(const ull*)(wrow + 2 * i);
        wr[25] = 0ull;
    }

    // Epilogue constants
    float wih0 = 0.f, wih1 = 0.f, bias = 0.f, wout = 0.f;
    int hoff = 0;
    if (tid < HH) {
        wih0 = Wih[2 * tid];
        wih1 = Wih[2 * tid + 1];
        bias = bih[tid] + bhh[tid];
        wout = Wout[tid];
        hoff = (tid / CW) * CS + (tid % CW);
    }
    const float bo = bOut[0];

    // Init h = 0 (including pad slots)
    for (int i = tid; i < NC * CS; i += 832) hsm[i] = 0.0f;
    __syncthreads();

    float myp = 0.0f;  // kc0 thread keeps its partial in a register

#pragma unroll 1
    for (int t = 0; t < TT; t++) {
        // ---- Phase A: dot partials (warps 0-24) + head reduce for t-1 (warp 25)
        if (compute) {
            const ulonglong2* hp = (const ulonglong2*)(hsm + CS * kc);  // 16B aligned
            ull a0 = 0ull, a1 = 0ull;
#pragma unroll
            for (int i = 0; i < 13; i++) {
                ulonglong2 hv = hp[i];          // LDS.128, conflict-free
                fma2(a0, hv.x, wr[2 * i]);
                fma2(a1, hv.y, wr[2 * i + 1]);
            }
            float s0, s1, s2, s3;
            unpack2(a0, s0, s1);
            unpack2(a1, s2, s3);
            float p = (s0 + s1) + (s2 + s3);
            if (kc == 0) myp = p;
            else         part[(kc - 1) * HH + j] = p;
        } else if (t > 0) {
            // out[t-1,b] = sum_j houtsm[(t-1)&1][j] + bout
            const float* hv = houtsm[(t - 1) & 1];
            float acc = 0.0f;
#pragma unroll
            for (int i = 0; i < 7; i++) {
                int idx = lane + 32 * i;
                if (idx < HH) acc += hv[idx];
            }
#pragma unroll
            for (int off = 16; off; off >>= 1)
                acc += __shfl_xor_sync(0xFFFFFFFFu, acc, off);
            if (lane == 0) out[(size_t)(t - 1) * BB + b] = acc + bo;
        }
        __syncthreads();

        // ---- Phase B: reduce + tanh + publish h (threads 0..199)
        if (tid < HH) {
            float s = myp + part[tid] + part[HH + tid] + part[2 * HH + tid];
            float2 xv = xsm[t];
            float pre = fmaf(xv.x, wih0, fmaf(xv.y, wih1, s + bias));
            float h = tanh_hw(pre);
            hsm[hoff] = h;
            houtsm[t & 1][tid] = h * wout;
        }
        __syncthreads();
    }

    // Final step's output (t = TT-1, parity 1)
    if (outwarp) {
        const float* hv = houtsm[(TT - 1) & 1];
        float acc = 0.0f;
#pragma unroll
        for (int i = 0; i < 7; i++) {
            int idx = lane + 32 * i;
            if (idx < HH) acc += hv[idx];
        }
#pragma unroll
        for (int off = 16; off; off >>= 1)
            acc += __shfl_xor_sync(0xFFFFFFFFu, acc, off);
        if (lane == 0) out[(size_t)(TT - 1) * BB + b] = acc + bo;
    }
}

extern "C" void kernel_launch(void* const* d_in, const int* in_sizes, int n_in,
                              void* d_out, int out_size) {
    const float* input_seq = (const float*)d_in[0];  // [T,B,2]
    const float* W_ih      = (const float*)d_in[1];  // [H,2]
    const float* W_hh      = (const float*)d_in[2];  // [H,H]
    const float* b_ih      = (const float*)d_in[3];  // [H]
    const float* b_hh      = (const float*)d_in[4];  // [H]
    const float* W_out     = (const float*)d_in[5];  // [1,H]
    const float* b_out     = (const float*)d_in[6];  // [1]
    float* out = (float*)d_out;                      // [T,B,1]

    rnn_kernel<<<BB, 832>>>(input_seq, W_ih, W_hh, b_ih, b_hh, W_out, b_out, out);
}